// round 13
// baseline (speedup 1.0000x reference)
#include <cuda_runtime.h>
#include <cstdint>

#define DIM 192
#define SLICE (DIM * DIM)
#define NV (DIM * DIM * DIM)
#define NPIX 125.0f
#define EPS 1e-5f

#define TX 32
#define TY 8
#define ZCHUNK 64
#define NSTEPS (ZCHUNK + 4)   // 68 planes swept per chunk (halo 2 each side)

#define TLX (TX + 4)          // 36 (x halo 2)
#define TLY (TY + 4)          // 12 (y halo 2)
#define TLXP 37               // padded row
#define NSTAGE (TLX * TLY)    // 432 staging elements

typedef unsigned long long u64;

__device__ __forceinline__ u64 pack2(float a, float b) {
  u64 r;
  asm("mov.b64 %0, {%1, %2};" : "=l"(r) : "f"(a), "f"(b));
  return r;
}
__device__ __forceinline__ float2 unpack2(u64 p) {
  float2 v;
  asm("mov.b64 {%0, %1}, %2;" : "=f"(v.x), "=f"(v.y) : "l"(p));
  return v;
}
#define ADD2(r, a, b) \
  asm("add.rn.f32x2 %0, %1, %2;" : "=l"(r) : "l"(a), "l"(b))
#define FMA2(r, a, b, c) \
  asm("fma.rn.f32x2 %0, %1, %2, %3;" : "=l"(r) : "l"(a), "l"(b), "l"(c))

__global__ void __launch_bounds__(256, 3) ncc_fused(
    const float* __restrict__ m, const float* __restrict__ f,
    const int* __restrict__ mmask, const int* __restrict__ fmask,
    float* __restrict__ out) {
  // 5-deep ring of (m,f) plane tiles with halo 2 — serves both the W-sum and
  // the z/y/x gradients. 5*12*37*8B = 17.8 KB.
  __shared__ float2 ring[5][TLY][TLXP];
  __shared__ float4 w4[TLY][TX];      // W-sums: (m,f) pair, (mm,ff) pair
  __shared__ float w1[TLY][TX + 1];   // W-sums: mf

  const int tid = threadIdx.x;
  const int tx = tid & 31;
  const int ty = tid >> 5;
  const int bx = blockIdx.x, by = blockIdx.y, bz = blockIdx.z;
  const int z0 = bz * ZCHUNK;
  const int zend = z0 + ZCHUNK - 1;
  const int gx = bx * TX + tx;
  const int gy = by * TY + ty;

  // Two staging slots per thread (NSTAGE=432, 256 threads).
  const int lx0 = tid % TLX, ly0 = tid / TLX;
  const int idx1 = tid + 256;
  const bool ok1 = idx1 < NSTAGE;
  const int lx1 = ok1 ? (idx1 % TLX) : 0, ly1 = ok1 ? (idx1 / TLX) : 0;
  const int ggx0 = bx * TX - 2 + lx0, ggy0 = by * TY - 2 + ly0;
  const int ggx1 = bx * TX - 2 + lx1, ggy1 = by * TY - 2 + ly1;
  const bool in0 = (unsigned)ggx0 < DIM && (unsigned)ggy0 < DIM;
  const bool in1 = ok1 && (unsigned)ggx1 < DIM && (unsigned)ggy1 < DIM;
  const size_t off0 = (size_t)ggy0 * DIM + ggx0;
  const size_t off1 = (size_t)ggy1 * DIM + ggx1;
  const size_t moff = (size_t)gy * DIM + gx;

  // W-sum assignments (384 points, 256 threads -> 1 + predicated 2nd).
  const int wxi0 = tid & 31, wly0 = tid >> 5;
  const int wxi1 = tid & 31, wly1 = (tid + 256) >> 5;
  const bool wok1 = (tid + 256) < TX * TLY;

  const u64 NEG1 = pack2(-1.0f, -1.0f);

  // Prefetch registers: next plane's data + next output's masks.
  float pa0 = 0.f, pb0 = 0.f, pa1 = 0.f, pb1 = 0.f;
  int pmm = 0, pff = 0;
  {
    const int zp = z0 - 2;  // plane for step 0
    if (zp >= 0) {
      const size_t pb_ = (size_t)zp * SLICE;
      if (in0) { pa0 = m[pb_ + off0]; pb0 = f[pb_ + off0]; }
      if (in1) { pa1 = m[pb_ + off1]; pb1 = f[pb_ + off1]; }
    }
  }

  // Sliding 5-plane D-window: per-phase registers (compile-time index under
  // the inner unroll -> no shift moves). Pairs: (m,f) and (mm,ff); mf scalar.
  u64 rp_mf[5], rp_sq[5];
  float rp_s[5];
  u64 acc_mf = 0ull, acc_sq = 0ull;
  float acc_s = 0.f;
#pragma unroll
  for (int p = 0; p < 5; p++) { rp_mf[p] = 0ull; rp_sq[p] = 0ull; rp_s[p] = 0.f; }

  // Incrementally maintained base for the NEXT prefetch plane (z0-1 at entry).
  size_t nbase = (size_t)(z0 - 1) * SLICE;

#pragma unroll 1
  for (int o = 0; o < 14; o++) {   // 14*5 = 70 >= NSTEPS(68); tail steps no-op
#pragma unroll
    for (int ph = 0; ph < 5; ph++) {
      const int step = o * 5 + ph;
      const int zp = z0 - 2 + step;
      const bool active = (step < NSTEPS) && (zp >= 0) && (zp < DIM);
      // Capture this step's masks before the prefetch overwrites them.
      const int cmm = pmm, cff = pff;
      u64 h_mf = 0ull, h_sq = 0ull;
      float h_s = 0.f;

      if (active) {
        const int s = zp % 5;
        // Stage the prefetched plane into the ring slot.
        ring[s][ly0][lx0] = make_float2(pa0, pb0);
        if (ok1) ring[s][ly1][lx1] = make_float2(pa1, pb1);
        __syncthreads();
        // W-direction 5-tap sums (packed f32x2): pass 1.
        {
          u64 smf = 0ull, ssq = 0ull;
          float ss = 0.f;
#pragma unroll
          for (int d = 0; d < 5; d++) {
            float2 ab = ring[s][wly0][wxi0 + d];
            u64 abp = pack2(ab.x, ab.y);
            ADD2(smf, smf, abp);
            FMA2(ssq, abp, abp, ssq);
            ss = fmaf(ab.x, ab.y, ss);
          }
          float2 a = unpack2(smf), b = unpack2(ssq);
          w4[wly0][wxi0] = make_float4(a.x, a.y, b.x, b.y);
          w1[wly0][wxi0] = ss;
        }
        // Pass 2 (predicated).
        if (wok1) {
          u64 smf = 0ull, ssq = 0ull;
          float ss = 0.f;
#pragma unroll
          for (int d = 0; d < 5; d++) {
            float2 ab = ring[s][wly1][wxi1 + d];
            u64 abp = pack2(ab.x, ab.y);
            ADD2(smf, smf, abp);
            FMA2(ssq, abp, abp, ssq);
            ss = fmaf(ab.x, ab.y, ss);
          }
          float2 a = unpack2(smf), b = unpack2(ssq);
          w4[wly1][wxi1] = make_float4(a.x, a.y, b.x, b.y);
          w1[wly1][wxi1] = ss;
        }
      }

      // Prefetch next plane + next output's masks (overlaps the W-sum work).
      {
        const int zpn = zp + 1;
        if (step + 1 < NSTEPS && zpn >= 0 && zpn < DIM) {
          if (in0) { pa0 = m[nbase + off0]; pb0 = f[nbase + off0]; }
          if (in1) { pa1 = m[nbase + off1]; pb1 = f[nbase + off1]; }
        }
        const int zon = zpn - 2;
        if (zon >= z0 && zon <= zend) {
          const size_t mb = (size_t)zon * SLICE + moff;
          pmm = mmask[mb];
          pff = fmask[mb];
        }
        nbase += SLICE;
      }

      if (active) {
        __syncthreads();
        // H-direction 5-tap sums (packed).
#pragma unroll
        for (int d = 0; d < 5; d++) {
          float4 v = w4[ty + d][tx];
          u64 vmf = pack2(v.x, v.y);
          u64 vsq = pack2(v.z, v.w);
          ADD2(h_mf, h_mf, vmf);
          ADD2(h_sq, h_sq, vsq);
          h_s += w1[ty + d][tx];
        }
      }

      // Slide the D-window: acc += h - rp[ph]; rp[ph] = h. (compile-time ph)
      ADD2(acc_mf, acc_mf, h_mf);
      FMA2(acc_mf, rp_mf[ph], NEG1, acc_mf);
      rp_mf[ph] = h_mf;
      ADD2(acc_sq, acc_sq, h_sq);
      FMA2(acc_sq, rp_sq[ph], NEG1, acc_sq);
      rp_sq[ph] = h_sq;
      acc_s += h_s - rp_s[ph];
      rp_s[ph] = h_s;

      const int z_out = zp - 2;
      if (z_out >= z0 && z_out <= zend) {
        const float2 amf = unpack2(acc_mf);
        const float2 asq = unpack2(acc_sq);
        const float sum_m = amf.x, sum_f = amf.y;
        const float sum_mm = asq.x, sum_ff = asq.y;
        const float sum_mf = acc_s;
        const float mmean = sum_m / NPIX;
        const float fmean = sum_f / NPIX;
        const float var_m = sum_mm - 2.0f * mmean * sum_m + NPIX * mmean * mmean;
        const float var_f = sum_ff - 2.0f * fmean * sum_f + NPIX * fmean * fmean;
        const float var_mf = var_m * var_f;
        const float cross =
            sum_mf - fmean * sum_m - mmean * sum_f + NPIX * mmean * fmean;

        const int lx = tx + 2, lyy = ty + 2;  // halo-2 offsets
        const int pc = z_out % 5;
        const int pm_ = (z_out + 4) % 5;
        const int pp_ = (z_out + 1) % 5;
        float2 c = ring[pc][lyy][lx];
        float mc = c.x - mmean, fc = c.y - fmean;

        bool valid =
            (var_mf > EPS) && (var_f > EPS) && (fc != 0.0f) && (mc != 0.0f);
        float factor = 0.0f;
        if (valid) factor = 2.0f * cross / var_mf * (mc - cross * fc / var_f);

        const size_t i = (size_t)z_out * SLICE + moff;
        const float u = ((cmm | cff) != 0) ? 1.0f : 0.0f;
        const float scale = -0.5f * factor * u;

        // jnp.gradient: central diff interior, one-sided edges.
        float gD, gH, gW;
        if (z_out == 0) {
          float2 a = ring[pp_][lyy][lx];
          gD = (a.x - c.x) + (a.y - c.y);
        } else if (z_out == DIM - 1) {
          float2 b = ring[pm_][lyy][lx];
          gD = (c.x - b.x) + (c.y - b.y);
        } else {
          float2 a = ring[pp_][lyy][lx];
          float2 b = ring[pm_][lyy][lx];
          gD = 0.5f * (a.x - b.x) + 0.5f * (a.y - b.y);
        }
        if (gy == 0) {
          float2 a = ring[pc][lyy + 1][lx];
          gH = (a.x - c.x) + (a.y - c.y);
        } else if (gy == DIM - 1) {
          float2 b = ring[pc][lyy - 1][lx];
          gH = (c.x - b.x) + (c.y - b.y);
        } else {
          float2 a = ring[pc][lyy + 1][lx];
          float2 b = ring[pc][lyy - 1][lx];
          gH = 0.5f * (a.x - b.x) + 0.5f * (a.y - b.y);
        }
        if (gx == 0) {
          float2 a = ring[pc][lyy][lx + 1];
          gW = (a.x - c.x) + (a.y - c.y);
        } else if (gx == DIM - 1) {
          float2 b = ring[pc][lyy][lx - 1];
          gW = (c.x - b.x) + (c.y - b.y);
        } else {
          float2 a = ring[pc][lyy][lx + 1];
          float2 b = ring[pc][lyy][lx - 1];
          gW = 0.5f * (a.x - b.x) + 0.5f * (a.y - b.y);
        }

        out[i] = scale * gD;
        out[(size_t)NV + i] = scale * gH;
        out[2 * (size_t)NV + i] = scale * gW;
      }
    }
  }
}

extern "C" void kernel_launch(void* const* d_in, const int* in_sizes, int n_in,
                              void* d_out, int out_size) {
  const float* moving = (const float*)d_in[0];
  const float* fixed_ = (const float*)d_in[1];
  const int* mmask = (const int*)d_in[2];
  const int* fmask = (const int*)d_in[3];
  float* out = (float*)d_out;

  dim3 grid(DIM / TX, DIM / TY, DIM / ZCHUNK);  // 6 x 24 x 3 = 432 blocks
  ncc_fused<<<grid, 256>>>(moving, fixed_, mmask, fmask, out);
}

// round 15
// speedup vs baseline: 1.0369x; 1.0369x over previous
#include <cuda_runtime.h>
#include <cstdint>

#define DIM 192
#define SLICE (DIM * DIM)
#define NV (DIM * DIM * DIM)
#define NPIX 125.0f
#define EPS 1e-5f

#define TX 32
#define TY 8
#define ZCHUNK 64
#define NSTEPS (ZCHUNK + 4)   // 68 planes swept per chunk (halo 2 each side)

#define TLX (TX + 4)          // 36 (x halo 2)
#define TLY (TY + 4)          // 12 (y halo 2)
#define TLXP 37               // padded row
#define NSTAGE (TLX * TLY)    // 432 staging elements

__global__ void __launch_bounds__(256, 3) ncc_fused(
    const float* __restrict__ m, const float* __restrict__ f,
    const int* __restrict__ mmask, const int* __restrict__ fmask,
    float* __restrict__ out) {
  // 5-deep ring of (m,f) plane tiles with halo 2 — serves both the W-sum and
  // the z/y/x gradients. 5*12*37*8B = 17.8 KB.
  __shared__ float2 ring[5][TLY][TLXP];
  __shared__ float4 w4[TLY][TX];      // W-sums: m,f,mm,ff
  __shared__ float w1[TLY][TX + 1];   // W-sums: mf

  const int tid = threadIdx.x;
  const int tx = tid & 31;
  const int ty = tid >> 5;
  const int bx = blockIdx.x, by = blockIdx.y, bz = blockIdx.z;
  const int z0 = bz * ZCHUNK;
  const int zend = z0 + ZCHUNK - 1;
  const int gx = bx * TX + tx;
  const int gy = by * TY + ty;

  // Two staging slots per thread (NSTAGE=432, 256 threads).
  const int lx0 = tid % TLX, ly0 = tid / TLX;
  const int idx1 = tid + 256;
  const bool ok1 = idx1 < NSTAGE;
  const int lx1 = ok1 ? (idx1 % TLX) : 0, ly1 = ok1 ? (idx1 / TLX) : 0;
  const int ggx0 = bx * TX - 2 + lx0, ggy0 = by * TY - 2 + ly0;
  const int ggx1 = bx * TX - 2 + lx1, ggy1 = by * TY - 2 + ly1;
  const bool in0 = (unsigned)ggx0 < DIM && (unsigned)ggy0 < DIM;
  const bool in1 = ok1 && (unsigned)ggx1 < DIM && (unsigned)ggy1 < DIM;
  const size_t off0 = (size_t)ggy0 * DIM + ggx0;
  const size_t off1 = (size_t)ggy1 * DIM + ggx1;
  const size_t moff = (size_t)gy * DIM + gx;

  // W-sum assignments (384 points, 256 threads -> 1 + predicated 2nd).
  const int wxi0 = tid & 31, wly0 = tid >> 5;
  const int wxi1 = tid & 31, wly1 = (tid + 256) >> 5;
  const bool wok1 = (tid + 256) < TX * TLY;

  // Prefetch registers: next plane's data + next output's masks.
  float pa0 = 0.f, pb0 = 0.f, pa1 = 0.f, pb1 = 0.f;
  int pmm = 0, pff = 0;
  {
    const int zp = z0 - 2;  // plane for step 0
    if (zp >= 0) {
      const size_t pb_ = (size_t)zp * SLICE;
      if (in0) { pa0 = m[pb_ + off0]; pb0 = f[pb_ + off0]; }
      if (in1) { pa1 = m[pb_ + off1]; pb1 = f[pb_ + off1]; }
    }
  }

  // Sliding 5-plane D-window: phase-indexed register ring (compile-time index
  // under the inner unroll -> no shift moves). Same scalar math as R12.
  float rh[5][5];
  float acc0 = 0.f, acc1 = 0.f, acc2 = 0.f, acc3 = 0.f, acc4 = 0.f;
#pragma unroll
  for (int p = 0; p < 5; p++) {
#pragma unroll
    for (int q = 0; q < 5; q++) rh[p][q] = 0.f;
  }

  // Incrementally maintained base for the NEXT prefetch plane (z0-1 at entry).
  size_t nbase = (size_t)(z0 - 1) * SLICE;

#pragma unroll 1
  for (int o = 0; o < 14; o++) {   // 14*5 = 70 >= NSTEPS(68); tail steps no-op
#pragma unroll
    for (int ph = 0; ph < 5; ph++) {
      const int step = o * 5 + ph;
      const int zp = z0 - 2 + step;
      const bool active = (step < NSTEPS) && (zp >= 0) && (zp < DIM);
      // Capture this step's masks before the prefetch overwrites them.
      const int cmm = pmm, cff = pff;
      float h0 = 0.f, h1 = 0.f, h2 = 0.f, h3 = 0.f, h4 = 0.f;

      if (active) {
        const int s = zp % 5;
        // Stage the prefetched plane into the ring slot.
        ring[s][ly0][lx0] = make_float2(pa0, pb0);
        if (ok1) ring[s][ly1][lx1] = make_float2(pa1, pb1);
        __syncthreads();
        // W-direction 5-tap sums of the 5 product fields (2 explicit passes).
        {
          float sm = 0.f, sf = 0.f, smm = 0.f, sff = 0.f, smf = 0.f;
#pragma unroll
          for (int d = 0; d < 5; d++) {
            float2 ab = ring[s][wly0][wxi0 + d];
            sm += ab.x;
            sf += ab.y;
            smm += ab.x * ab.x;
            sff += ab.y * ab.y;
            smf += ab.x * ab.y;
          }
          w4[wly0][wxi0] = make_float4(sm, sf, smm, sff);
          w1[wly0][wxi0] = smf;
        }
        if (wok1) {
          float sm = 0.f, sf = 0.f, smm = 0.f, sff = 0.f, smf = 0.f;
#pragma unroll
          for (int d = 0; d < 5; d++) {
            float2 ab = ring[s][wly1][wxi1 + d];
            sm += ab.x;
            sf += ab.y;
            smm += ab.x * ab.x;
            sff += ab.y * ab.y;
            smf += ab.x * ab.y;
          }
          w4[wly1][wxi1] = make_float4(sm, sf, smm, sff);
          w1[wly1][wxi1] = smf;
        }
      }

      // Prefetch next plane + next output's masks (overlaps the W-sum work).
      {
        const int zpn = zp + 1;
        if (step + 1 < NSTEPS && zpn >= 0 && zpn < DIM) {
          if (in0) { pa0 = m[nbase + off0]; pb0 = f[nbase + off0]; }
          if (in1) { pa1 = m[nbase + off1]; pb1 = f[nbase + off1]; }
        }
        const int zon = zpn - 2;
        if (zon >= z0 && zon <= zend) {
          const size_t mb = (size_t)zon * SLICE + moff;
          pmm = mmask[mb];
          pff = fmask[mb];
        }
        nbase += SLICE;
      }

      if (active) {
        __syncthreads();
        // H-direction 5-tap sums for this thread's (x,y).
#pragma unroll
        for (int d = 0; d < 5; d++) {
          float4 v = w4[ty + d][tx];
          h0 += v.x;
          h1 += v.y;
          h2 += v.z;
          h3 += v.w;
          h4 += w1[ty + d][tx];
        }
      }

      // Slide the D-window: acc += h - rh[ph]; rh[ph] = h (compile-time ph).
      acc0 += h0 - rh[ph][0]; rh[ph][0] = h0;
      acc1 += h1 - rh[ph][1]; rh[ph][1] = h1;
      acc2 += h2 - rh[ph][2]; rh[ph][2] = h2;
      acc3 += h3 - rh[ph][3]; rh[ph][3] = h3;
      acc4 += h4 - rh[ph][4]; rh[ph][4] = h4;

      const int z_out = zp - 2;
      if (z_out >= z0 && z_out <= zend) {
        const float sum_m = acc0, sum_f = acc1, sum_mm = acc2,
                    sum_ff = acc3, sum_mf = acc4;
        const float mmean = sum_m / NPIX;
        const float fmean = sum_f / NPIX;
        const float var_m = sum_mm - 2.0f * mmean * sum_m + NPIX * mmean * mmean;
        const float var_f = sum_ff - 2.0f * fmean * sum_f + NPIX * fmean * fmean;
        const float var_mf = var_m * var_f;
        const float cross =
            sum_mf - fmean * sum_m - mmean * sum_f + NPIX * mmean * fmean;

        const int lx = tx + 2, lyy = ty + 2;  // halo-2 offsets
        const int pc = z_out % 5;
        const int pm_ = (z_out + 4) % 5;
        const int pp_ = (z_out + 1) % 5;
        float2 c = ring[pc][lyy][lx];
        float mc = c.x - mmean, fc = c.y - fmean;

        bool valid =
            (var_mf > EPS) && (var_f > EPS) && (fc != 0.0f) && (mc != 0.0f);
        float factor = 0.0f;
        if (valid) factor = 2.0f * cross / var_mf * (mc - cross * fc / var_f);

        const size_t i = (size_t)z_out * SLICE + moff;
        const float u = ((cmm | cff) != 0) ? 1.0f : 0.0f;
        const float scale = -0.5f * factor * u;

        // jnp.gradient: central diff interior, one-sided edges.
        float gD, gH, gW;
        if (z_out == 0) {
          float2 a = ring[pp_][lyy][lx];
          gD = (a.x - c.x) + (a.y - c.y);
        } else if (z_out == DIM - 1) {
          float2 b = ring[pm_][lyy][lx];
          gD = (c.x - b.x) + (c.y - b.y);
        } else {
          float2 a = ring[pp_][lyy][lx];
          float2 b = ring[pm_][lyy][lx];
          gD = 0.5f * (a.x - b.x) + 0.5f * (a.y - b.y);
        }
        if (gy == 0) {
          float2 a = ring[pc][lyy + 1][lx];
          gH = (a.x - c.x) + (a.y - c.y);
        } else if (gy == DIM - 1) {
          float2 b = ring[pc][lyy - 1][lx];
          gH = (c.x - b.x) + (c.y - b.y);
        } else {
          float2 a = ring[pc][lyy + 1][lx];
          float2 b = ring[pc][lyy - 1][lx];
          gH = 0.5f * (a.x - b.x) + 0.5f * (a.y - b.y);
        }
        if (gx == 0) {
          float2 a = ring[pc][lyy][lx + 1];
          gW = (a.x - c.x) + (a.y - c.y);
        } else if (gx == DIM - 1) {
          float2 b = ring[pc][lyy][lx - 1];
          gW = (c.x - b.x) + (c.y - b.y);
        } else {
          float2 a = ring[pc][lyy][lx + 1];
          float2 b = ring[pc][lyy][lx - 1];
          gW = 0.5f * (a.x - b.x) + 0.5f * (a.y - b.y);
        }

        out[i] = scale * gD;
        out[(size_t)NV + i] = scale * gH;
        out[2 * (size_t)NV + i] = scale * gW;
      }
    }
  }
}

extern "C" void kernel_launch(void* const* d_in, const int* in_sizes, int n_in,
                              void* d_out, int out_size) {
  const float* moving = (const float*)d_in[0];
  const float* fixed_ = (const float*)d_in[1];
  const int* mmask = (const int*)d_in[2];
  const int* fmask = (const int*)d_in[3];
  float* out = (float*)d_out;

  dim3 grid(DIM / TX, DIM / TY, DIM / ZCHUNK);  // 6 x 24 x 3 = 432 blocks
  ncc_fused<<<grid, 256>>>(moving, fixed_, mmask, fmask, out);
}

// round 16
// speedup vs baseline: 1.2536x; 1.2090x over previous
#include <cuda_runtime.h>
#include <cstdint>

#define DIM 192
#define SLICE (DIM * DIM)
#define NV (DIM * DIM * DIM)
#define NPIX 125.0f
#define EPS 1e-5f

#define TX 32
#define TY 12
#define NTHR 384
#define ZCHUNK 64
#define NSTEPS (ZCHUNK + 4)   // 68 planes swept per chunk (halo 2 each side)

#define TLX (TX + 4)          // 36 (x halo 2)
#define TLY (TY + 4)          // 16 (y halo 2)
#define TLXP 37               // padded row
#define NSTAGE (TLX * TLY)    // 576 staging elements = 384 * 1.5

__global__ void __launch_bounds__(NTHR, 2) ncc_fused(
    const float* __restrict__ m, const float* __restrict__ f,
    const int* __restrict__ mmask, const int* __restrict__ fmask,
    float* __restrict__ out) {
  // 5-deep ring of (m,f) plane tiles with halo 2 — serves both the W-sum and
  // the z/y/x gradients. 5*16*37*8B = 23.7 KB.
  __shared__ float2 ring[5][TLY][TLXP];
  __shared__ float4 w4[TLY][TX];      // W-sums: m,f,mm,ff
  __shared__ float w1[TLY][TX + 1];   // W-sums: mf

  const int tid = threadIdx.x;
  const int tx = tid & 31;
  const int ty = tid >> 5;            // 0..11
  const int bx = blockIdx.x, by = blockIdx.y, bz = blockIdx.z;
  const int z0 = bz * ZCHUNK;
  const int zend = z0 + ZCHUNK - 1;
  const int gx = bx * TX + tx;
  const int gy = by * TY + ty;

  // Two staging slots per thread (NSTAGE=576, 384 threads -> 1 + tid<192).
  const int lx0 = tid % TLX, ly0 = tid / TLX;
  const int idx1 = tid + NTHR;
  const bool ok1 = idx1 < NSTAGE;     // tid < 192
  const int lx1 = ok1 ? (idx1 % TLX) : 0, ly1 = ok1 ? (idx1 / TLX) : 0;
  const int ggx0 = bx * TX - 2 + lx0, ggy0 = by * TY - 2 + ly0;
  const int ggx1 = bx * TX - 2 + lx1, ggy1 = by * TY - 2 + ly1;
  const bool in0 = (unsigned)ggx0 < DIM && (unsigned)ggy0 < DIM;
  const bool in1 = ok1 && (unsigned)ggx1 < DIM && (unsigned)ggy1 < DIM;
  const size_t off0 = (size_t)ggy0 * DIM + ggx0;
  const size_t off1 = (size_t)ggy1 * DIM + ggx1;
  const size_t moff = (size_t)gy * DIM + gx;

  // W-sum assignments (512 points, 384 threads -> 1 + tid<128).
  const int wxi0 = tid & 31, wly0 = tid >> 5;              // rows 0..11
  const int wxi1 = (tid + NTHR) & 31, wly1 = (tid + NTHR) >> 5;  // rows 12..15
  const bool wok1 = (tid + NTHR) < TX * TLY;               // tid < 128

  // Prefetch registers: next plane's data + next output's masks.
  float pa0 = 0.f, pb0 = 0.f, pa1 = 0.f, pb1 = 0.f;
  int pmm = 0, pff = 0;
  {
    const int zp = z0 - 2;  // plane for step 0
    if (zp >= 0) {
      const size_t pb_ = (size_t)zp * SLICE;
      if (in0) { pa0 = m[pb_ + off0]; pb0 = f[pb_ + off0]; }
      if (in1) { pa1 = m[pb_ + off1]; pb1 = f[pb_ + off1]; }
    }
  }

  // Sliding 5-plane D-window as shift registers (oldest = s0, newest = s4).
  float s0_0 = 0.f, s0_1 = 0.f, s0_2 = 0.f, s0_3 = 0.f, s0_4 = 0.f;
  float s1_0 = 0.f, s1_1 = 0.f, s1_2 = 0.f, s1_3 = 0.f, s1_4 = 0.f;
  float s2_0 = 0.f, s2_1 = 0.f, s2_2 = 0.f, s2_3 = 0.f, s2_4 = 0.f;
  float s3_0 = 0.f, s3_1 = 0.f, s3_2 = 0.f, s3_3 = 0.f, s3_4 = 0.f;
  float s4_0 = 0.f, s4_1 = 0.f, s4_2 = 0.f, s4_3 = 0.f, s4_4 = 0.f;
  float acc0 = 0.f, acc1 = 0.f, acc2 = 0.f, acc3 = 0.f, acc4 = 0.f;

  // Incrementally maintained base for the NEXT prefetch plane (z0-1 at entry).
  size_t nbase = (size_t)(z0 - 1) * SLICE;

#pragma unroll 1
  for (int step = 0; step < NSTEPS; step++) {
    const int zp = z0 - 2 + step;
    const bool active = (zp >= 0) && (zp < DIM);
    // Capture this step's masks before the prefetch overwrites them.
    const int cmm = pmm, cff = pff;
    float h0 = 0.f, h1 = 0.f, h2 = 0.f, h3 = 0.f, h4 = 0.f;

    if (active) {
      const int s = zp % 5;
      // Stage the prefetched plane into the ring slot.
      ring[s][ly0][lx0] = make_float2(pa0, pb0);
      if (ok1) ring[s][ly1][lx1] = make_float2(pa1, pb1);
      __syncthreads();
      // W-direction 5-tap sums of the 5 product fields (2 explicit passes).
      {
        float sm = 0.f, sf = 0.f, smm = 0.f, sff = 0.f, smf = 0.f;
#pragma unroll
        for (int d = 0; d < 5; d++) {
          float2 ab = ring[s][wly0][wxi0 + d];
          sm += ab.x;
          sf += ab.y;
          smm += ab.x * ab.x;
          sff += ab.y * ab.y;
          smf += ab.x * ab.y;
        }
        w4[wly0][wxi0] = make_float4(sm, sf, smm, sff);
        w1[wly0][wxi0] = smf;
      }
      if (wok1) {
        float sm = 0.f, sf = 0.f, smm = 0.f, sff = 0.f, smf = 0.f;
#pragma unroll
        for (int d = 0; d < 5; d++) {
          float2 ab = ring[s][wly1][wxi1 + d];
          sm += ab.x;
          sf += ab.y;
          smm += ab.x * ab.x;
          sff += ab.y * ab.y;
          smf += ab.x * ab.y;
        }
        w4[wly1][wxi1] = make_float4(sm, sf, smm, sff);
        w1[wly1][wxi1] = smf;
      }
    }

    // Prefetch next plane + next output's masks (overlaps the W-sum work).
    {
      const int zpn = zp + 1;
      if (step + 1 < NSTEPS && zpn >= 0 && zpn < DIM) {
        if (in0) { pa0 = m[nbase + off0]; pb0 = f[nbase + off0]; }
        if (in1) { pa1 = m[nbase + off1]; pb1 = f[nbase + off1]; }
      }
      const int zon = zpn - 2;
      if (zon >= z0 && zon <= zend) {
        const size_t mb = (size_t)zon * SLICE + moff;
        pmm = mmask[mb];
        pff = fmask[mb];
      }
      nbase += SLICE;
    }

    if (active) {
      __syncthreads();
      // H-direction 5-tap sums for this thread's (x,y).
#pragma unroll
      for (int d = 0; d < 5; d++) {
        float4 v = w4[ty + d][tx];
        h0 += v.x;
        h1 += v.y;
        h2 += v.z;
        h3 += v.w;
        h4 += w1[ty + d][tx];
      }
    }

    // Slide the D-window: add the new plane, drop the 5-steps-old plane.
    acc0 += h0 - s0_0; acc1 += h1 - s0_1; acc2 += h2 - s0_2;
    acc3 += h3 - s0_3; acc4 += h4 - s0_4;
    s0_0 = s1_0; s0_1 = s1_1; s0_2 = s1_2; s0_3 = s1_3; s0_4 = s1_4;
    s1_0 = s2_0; s1_1 = s2_1; s1_2 = s2_2; s1_3 = s2_3; s1_4 = s2_4;
    s2_0 = s3_0; s2_1 = s3_1; s2_2 = s3_2; s2_3 = s3_3; s2_4 = s3_4;
    s3_0 = s4_0; s3_1 = s4_1; s3_2 = s4_2; s3_3 = s4_3; s3_4 = s4_4;
    s4_0 = h0; s4_1 = h1; s4_2 = h2; s4_3 = h3; s4_4 = h4;

    const int z_out = zp - 2;
    if (z_out >= z0 && z_out <= zend) {
      const float sum_m = acc0, sum_f = acc1, sum_mm = acc2,
                  sum_ff = acc3, sum_mf = acc4;
      const float mmean = sum_m / NPIX;
      const float fmean = sum_f / NPIX;
      const float var_m = sum_mm - 2.0f * mmean * sum_m + NPIX * mmean * mmean;
      const float var_f = sum_ff - 2.0f * fmean * sum_f + NPIX * fmean * fmean;
      const float var_mf = var_m * var_f;
      const float cross =
          sum_mf - fmean * sum_m - mmean * sum_f + NPIX * mmean * fmean;

      const int lx = tx + 2, lyy = ty + 2;  // halo-2 offsets
      const int pc = z_out % 5;
      const int pm_ = (z_out + 4) % 5;
      const int pp_ = (z_out + 1) % 5;
      float2 c = ring[pc][lyy][lx];
      float mc = c.x - mmean, fc = c.y - fmean;

      bool valid =
          (var_mf > EPS) && (var_f > EPS) && (fc != 0.0f) && (mc != 0.0f);
      float factor = 0.0f;
      if (valid) factor = 2.0f * cross / var_mf * (mc - cross * fc / var_f);

      const size_t i = (size_t)z_out * SLICE + moff;
      const float u = ((cmm | cff) != 0) ? 1.0f : 0.0f;
      const float scale = -0.5f * factor * u;

      // jnp.gradient: central diff interior, one-sided edges.
      float gD, gH, gW;
      if (z_out == 0) {
        float2 a = ring[pp_][lyy][lx];
        gD = (a.x - c.x) + (a.y - c.y);
      } else if (z_out == DIM - 1) {
        float2 b = ring[pm_][lyy][lx];
        gD = (c.x - b.x) + (c.y - b.y);
      } else {
        float2 a = ring[pp_][lyy][lx];
        float2 b = ring[pm_][lyy][lx];
        gD = 0.5f * (a.x - b.x) + 0.5f * (a.y - b.y);
      }
      if (gy == 0) {
        float2 a = ring[pc][lyy + 1][lx];
        gH = (a.x - c.x) + (a.y - c.y);
      } else if (gy == DIM - 1) {
        float2 b = ring[pc][lyy - 1][lx];
        gH = (c.x - b.x) + (c.y - b.y);
      } else {
        float2 a = ring[pc][lyy + 1][lx];
        float2 b = ring[pc][lyy - 1][lx];
        gH = 0.5f * (a.x - b.x) + 0.5f * (a.y - b.y);
      }
      if (gx == 0) {
        float2 a = ring[pc][lyy][lx + 1];
        gW = (a.x - c.x) + (a.y - c.y);
      } else if (gx == DIM - 1) {
        float2 b = ring[pc][lyy][lx - 1];
        gW = (c.x - b.x) + (c.y - b.y);
      } else {
        float2 a = ring[pc][lyy][lx + 1];
        float2 b = ring[pc][lyy][lx - 1];
        gW = 0.5f * (a.x - b.x) + 0.5f * (a.y - b.y);
      }

      out[i] = scale * gD;
      out[(size_t)NV + i] = scale * gH;
      out[2 * (size_t)NV + i] = scale * gW;
    }
  }
}

extern "C" void kernel_launch(void* const* d_in, const int* in_sizes, int n_in,
                              void* d_out, int out_size) {
  const float* moving = (const float*)d_in[0];
  const float* fixed_ = (const float*)d_in[1];
  const int* mmask = (const int*)d_in[2];
  const int* fmask = (const int*)d_in[3];
  float* out = (float*)d_out;

  dim3 grid(DIM / TX, DIM / TY, DIM / ZCHUNK);  // 6 x 16 x 3 = 288 blocks
  ncc_fused<<<grid, NTHR>>>(moving, fixed_, mmask, fmask, out);
}

// round 17
// speedup vs baseline: 1.2656x; 1.0095x over previous
#include <cuda_runtime.h>
#include <cstdint>

#define DIM 192
#define SLICE (DIM * DIM)
#define NV (DIM * DIM * DIM)
#define RNPIX (1.0f / 125.0f)
#define NPIX 125.0f
#define EPS 1e-5f

#define TX 32
#define TY 8
#define ZCHUNK 64
#define NSTEPS (ZCHUNK + 4)   // 68 planes swept per chunk (halo 2 each side)

#define TLX (TX + 4)          // 36 (x halo 2)
#define TLY (TY + 4)          // 12 (y halo 2)
#define TLXP 37               // padded row
#define NSTAGE (TLX * TLY)    // 432 staging elements

__global__ void __launch_bounds__(256, 3) ncc_fused(
    const float* __restrict__ m, const float* __restrict__ f,
    const int* __restrict__ mmask, const int* __restrict__ fmask,
    float* __restrict__ out) {
  // 5-deep ring of (m,f) plane tiles with halo 2 — serves both the W-sum and
  // the z/y/x gradients. 5*12*37*8B = 17.8 KB.
  __shared__ float2 ring[5][TLY][TLXP];
  __shared__ float4 w4[TLY][TX];      // W-sums: m,f,mm,ff
  __shared__ float w1[TLY][TX + 1];   // W-sums: mf

  const int tid = threadIdx.x;
  const int tx = tid & 31;
  const int ty = tid >> 5;
  const int bx = blockIdx.x, by = blockIdx.y, bz = blockIdx.z;
  const int z0 = bz * ZCHUNK;
  const int zend = z0 + ZCHUNK - 1;
  const int gx = bx * TX + tx;
  const int gy = by * TY + ty;

  // Two staging slots per thread (NSTAGE=432, 256 threads).
  const int lx0 = tid % TLX, ly0 = tid / TLX;
  const int idx1 = tid + 256;
  const bool ok1 = idx1 < NSTAGE;
  const int lx1 = ok1 ? (idx1 % TLX) : 0, ly1 = ok1 ? (idx1 / TLX) : 0;
  const int ggx0 = bx * TX - 2 + lx0, ggy0 = by * TY - 2 + ly0;
  const int ggx1 = bx * TX - 2 + lx1, ggy1 = by * TY - 2 + ly1;
  const bool in0 = (unsigned)ggx0 < DIM && (unsigned)ggy0 < DIM;
  const bool in1 = ok1 && (unsigned)ggx1 < DIM && (unsigned)ggy1 < DIM;
  const size_t off0 = (size_t)ggy0 * DIM + ggx0;
  const size_t off1 = (size_t)ggy1 * DIM + ggx1;
  const size_t moff = (size_t)gy * DIM + gx;

  // W-sum assignments (384 points, 256 threads -> 1 + predicated 2nd).
  const int wxi0 = tid & 31, wly0 = tid >> 5;
  const int wxi1 = tid & 31, wly1 = (tid + 256) >> 5;
  const bool wok1 = (tid + 256) < TX * TLY;

  // Prefetch registers: next plane's data + next output's masks.
  float pa0 = 0.f, pb0 = 0.f, pa1 = 0.f, pb1 = 0.f;
  int pmm = 0, pff = 0;
  {
    const int zp = z0 - 2;  // plane for step 0
    if (zp >= 0) {
      const size_t pb_ = (size_t)zp * SLICE;
      if (in0) { pa0 = m[pb_ + off0]; pb0 = f[pb_ + off0]; }
      if (in1) { pa1 = m[pb_ + off1]; pb1 = f[pb_ + off1]; }
    }
  }

  // Sliding 5-plane D-window as shift registers (oldest = s0, newest = s4).
  float s0_0 = 0.f, s0_1 = 0.f, s0_2 = 0.f, s0_3 = 0.f, s0_4 = 0.f;
  float s1_0 = 0.f, s1_1 = 0.f, s1_2 = 0.f, s1_3 = 0.f, s1_4 = 0.f;
  float s2_0 = 0.f, s2_1 = 0.f, s2_2 = 0.f, s2_3 = 0.f, s2_4 = 0.f;
  float s3_0 = 0.f, s3_1 = 0.f, s3_2 = 0.f, s3_3 = 0.f, s3_4 = 0.f;
  float s4_0 = 0.f, s4_1 = 0.f, s4_2 = 0.f, s4_3 = 0.f, s4_4 = 0.f;
  float acc0 = 0.f, acc1 = 0.f, acc2 = 0.f, acc3 = 0.f, acc4 = 0.f;

  // Incrementally maintained base for the NEXT prefetch plane (z0-1 at entry).
  size_t nbase = (size_t)(z0 - 1) * SLICE;

#pragma unroll 1
  for (int step = 0; step < NSTEPS; step++) {
    const int zp = z0 - 2 + step;
    const bool active = (zp >= 0) && (zp < DIM);
    // Capture this step's masks before the prefetch overwrites them.
    const int cmm = pmm, cff = pff;
    float h0 = 0.f, h1 = 0.f, h2 = 0.f, h3 = 0.f, h4 = 0.f;

    if (active) {
      const int s = zp % 5;
      // Stage the prefetched plane into the ring slot.
      ring[s][ly0][lx0] = make_float2(pa0, pb0);
      if (ok1) ring[s][ly1][lx1] = make_float2(pa1, pb1);
      __syncthreads();
      // W-direction 5-tap sums of the 5 product fields (2 explicit passes).
      {
        float sm = 0.f, sf = 0.f, smm = 0.f, sff = 0.f, smf = 0.f;
#pragma unroll
        for (int d = 0; d < 5; d++) {
          float2 ab = ring[s][wly0][wxi0 + d];
          sm += ab.x;
          sf += ab.y;
          smm += ab.x * ab.x;
          sff += ab.y * ab.y;
          smf += ab.x * ab.y;
        }
        w4[wly0][wxi0] = make_float4(sm, sf, smm, sff);
        w1[wly0][wxi0] = smf;
      }
      if (wok1) {
        float sm = 0.f, sf = 0.f, smm = 0.f, sff = 0.f, smf = 0.f;
#pragma unroll
        for (int d = 0; d < 5; d++) {
          float2 ab = ring[s][wly1][wxi1 + d];
          sm += ab.x;
          sf += ab.y;
          smm += ab.x * ab.x;
          sff += ab.y * ab.y;
          smf += ab.x * ab.y;
        }
        w4[wly1][wxi1] = make_float4(sm, sf, smm, sff);
        w1[wly1][wxi1] = smf;
      }
    }

    // Prefetch next plane + next output's masks (overlaps the W-sum work).
    {
      const int zpn = zp + 1;
      if (step + 1 < NSTEPS && zpn >= 0 && zpn < DIM) {
        if (in0) { pa0 = m[nbase + off0]; pb0 = f[nbase + off0]; }
        if (in1) { pa1 = m[nbase + off1]; pb1 = f[nbase + off1]; }
      }
      const int zon = zpn - 2;
      if (zon >= z0 && zon <= zend) {
        const size_t mb = (size_t)zon * SLICE + moff;
        pmm = mmask[mb];
        pff = fmask[mb];
      }
      nbase += SLICE;
    }

    if (active) {
      __syncthreads();
      // H-direction 5-tap sums for this thread's (x,y).
#pragma unroll
      for (int d = 0; d < 5; d++) {
        float4 v = w4[ty + d][tx];
        h0 += v.x;
        h1 += v.y;
        h2 += v.z;
        h3 += v.w;
        h4 += w1[ty + d][tx];
      }
    }

    // Slide the D-window: add the new plane, drop the 5-steps-old plane.
    acc0 += h0 - s0_0; acc1 += h1 - s0_1; acc2 += h2 - s0_2;
    acc3 += h3 - s0_3; acc4 += h4 - s0_4;
    s0_0 = s1_0; s0_1 = s1_1; s0_2 = s1_2; s0_3 = s1_3; s0_4 = s1_4;
    s1_0 = s2_0; s1_1 = s2_1; s1_2 = s2_2; s1_3 = s2_3; s1_4 = s2_4;
    s2_0 = s3_0; s2_1 = s3_1; s2_2 = s3_2; s2_3 = s3_3; s2_4 = s3_4;
    s3_0 = s4_0; s3_1 = s4_1; s3_2 = s4_2; s3_3 = s4_3; s3_4 = s4_4;
    s4_0 = h0; s4_1 = h1; s4_2 = h2; s4_3 = h3; s4_4 = h4;

    const int z_out = zp - 2;
    if (z_out >= z0 && z_out <= zend) {
      const float sum_m = acc0, sum_f = acc1, sum_mm = acc2,
                  sum_ff = acc3, sum_mf = acc4;
      // Reciprocal-multiply instead of FDIV (125 is exact-ish; err ~1e-7).
      const float mmean = sum_m * RNPIX;
      const float fmean = sum_f * RNPIX;
      const float var_m = sum_mm - 2.0f * mmean * sum_m + NPIX * mmean * mmean;
      const float var_f = sum_ff - 2.0f * fmean * sum_f + NPIX * fmean * fmean;
      const float var_mf = var_m * var_f;
      const float cross =
          sum_mf - fmean * sum_m - mmean * sum_f + NPIX * mmean * fmean;

      const int lx = tx + 2, lyy = ty + 2;  // halo-2 offsets
      const int pc = z_out % 5;
      const int pm_ = (z_out + 4) % 5;
      const int pp_ = (z_out + 1) % 5;
      float2 c = ring[pc][lyy][lx];
      float mc = c.x - mmean, fc = c.y - fmean;

      bool valid =
          (var_mf > EPS) && (var_f > EPS) && (fc != 0.0f) && (mc != 0.0f);
      float factor = 0.0f;
      if (valid) {
        // Fast-approx divides (MUFU.RCP + mul): rel err ~2^-22, far inside
        // the 1e-3 gate.
        factor = 2.0f * __fdividef(cross, var_mf) *
                 (mc - __fdividef(cross * fc, var_f));
      }

      const size_t i = (size_t)z_out * SLICE + moff;
      const float u = ((cmm | cff) != 0) ? 1.0f : 0.0f;
      const float scale = -0.5f * factor * u;

      // jnp.gradient: central diff interior, one-sided edges.
      float gD, gH, gW;
      if (z_out == 0) {
        float2 a = ring[pp_][lyy][lx];
        gD = (a.x - c.x) + (a.y - c.y);
      } else if (z_out == DIM - 1) {
        float2 b = ring[pm_][lyy][lx];
        gD = (c.x - b.x) + (c.y - b.y);
      } else {
        float2 a = ring[pp_][lyy][lx];
        float2 b = ring[pm_][lyy][lx];
        gD = 0.5f * (a.x - b.x) + 0.5f * (a.y - b.y);
      }
      if (gy == 0) {
        float2 a = ring[pc][lyy + 1][lx];
        gH = (a.x - c.x) + (a.y - c.y);
      } else if (gy == DIM - 1) {
        float2 b = ring[pc][lyy - 1][lx];
        gH = (c.x - b.x) + (c.y - b.y);
      } else {
        float2 a = ring[pc][lyy + 1][lx];
        float2 b = ring[pc][lyy - 1][lx];
        gH = 0.5f * (a.x - b.x) + 0.5f * (a.y - b.y);
      }
      if (gx == 0) {
        float2 a = ring[pc][lyy][lx + 1];
        gW = (a.x - c.x) + (a.y - c.y);
      } else if (gx == DIM - 1) {
        float2 b = ring[pc][lyy][lx - 1];
        gW = (c.x - b.x) + (c.y - b.y);
      } else {
        float2 a = ring[pc][lyy][lx + 1];
        float2 b = ring[pc][lyy][lx - 1];
        gW = 0.5f * (a.x - b.x) + 0.5f * (a.y - b.y);
      }

      out[i] = scale * gD;
      out[(size_t)NV + i] = scale * gH;
      out[2 * (size_t)NV + i] = scale * gW;
    }
  }
}

extern "C" void kernel_launch(void* const* d_in, const int* in_sizes, int n_in,
                              void* d_out, int out_size) {
  const float* moving = (const float*)d_in[0];
  const float* fixed_ = (const float*)d_in[1];
  const int* mmask = (const int*)d_in[2];
  const int* fmask = (const int*)d_in[3];
  float* out = (float*)d_out;

  dim3 grid(DIM / TX, DIM / TY, DIM / ZCHUNK);  // 6 x 24 x 3 = 432 blocks
  ncc_fused<<<grid, 256>>>(moving, fixed_, mmask, fmask, out);
}